// round 11
// baseline (speedup 1.0000x reference)
#include <cuda_runtime.h>
#include <math.h>

// ============================================================================
// Actor_att1 — R10: 8-lane N-split groups, register-resident weights.
// warp = 4 groups x 8 lanes; group g handles row warp*4+g. Thread role t
// owns hidden floats {4t..4t+3} (32-wide) and output floats {2t,2t+1}
// (16-wide). Entity-encoder weights hoisted into registers (zero smem
// weight traffic inside the 31 entity iterations). h exchanged through a
// double-buffered stride-35 smem buffer (conflict-free, broadcast reads).
// ============================================================================

typedef unsigned long long u64;
#define DINL __device__ __forceinline__

DINL u64 f2pack(float lo, float hi){u64 d;asm("mov.b64 %0,{%1,%2};":"=l"(d):"f"(lo),"f"(hi));return d;}
DINL u64 f2splat(float v){u64 d;asm("mov.b64 %0,{%1,%1};":"=l"(d):"f"(v));return d;}
DINL void f2unpack(u64 v,float&lo,float&hi){asm("mov.b64 {%0,%1},%2;":"=f"(lo),"=f"(hi):"l"(v));}
DINL u64 f2fma(u64 a,u64 b,u64 c){u64 d;asm("fma.rn.f32x2 %0,%1,%2,%3;":"=l"(d):"l"(a),"l"(b),"l"(c));return d;}
DINL u64 f2mul(u64 a,u64 b){u64 d;asm("mul.rn.f32x2 %0,%1,%2;":"=l"(d):"l"(a),"l"(b));return d;}
DINL u64 f2add(u64 a,u64 b){u64 d;asm("add.rn.f32x2 %0,%1,%2;":"=l"(d):"l"(a),"l"(b));return d;}
DINL u64 sh1(u64 v){return __shfl_xor_sync(0xffffffffu,v,1);}
DINL u64 sh2(u64 v){return __shfl_xor_sync(0xffffffffu,v,2);}
DINL u64 sh4(u64 v){return __shfl_xor_sync(0xffffffffu,v,4);}
DINL float sf1(float v){return __shfl_xor_sync(0xffffffffu,v,1);}
DINL float sf2(float v){return __shfl_xor_sync(0xffffffffu,v,2);}
DINL float sf4(float v){return __shfl_xor_sync(0xffffffffu,v,4);}

#define NT 384
#define ROWS 48
#define OBS 127
#define HB 35            // h-exchange row stride (odd, 3 mod 32: conflict-free)

// smem weight block (original dense layouts; every field = multiple of 16B)
struct SW {
    float en_w1[4 * 32];  float en_b1[32];  float en_w2[32 * 16]; float en_b2[16];
    float oa_w1[5 * 32];  float oa_b1[32];  float oa_w2[32 * 16]; float oa_b2[16];
    float oa_g[16];       float oa_bln[16];
    float g_w1[3 * 32];   float g_b1[32];   float g_w2[32 * 16];  float g_b2[16];
    float g_g[16];        float g_bln[16];
    float m_w1[48 * 32];  float m_b1[32];   float m_w2[32 * 32];  float m_b2[32];
    float m_w3[32 * 2];   float m_b3[16];
};

DINL void cp_smem(float* dst, const float* __restrict__ src, int n, int tid) {
    for (int i = tid; i < n; i += NT) dst[i] = src[i];
}

// 8-lane reductions (within group: xor masks 4,2,1 stay inside the group)
DINL float red8(float v) { v += sf4(v); v += sf2(v); v += sf1(v); return v; }

__global__ void __launch_bounds__(NT, 1)
actor_kernel(const float* __restrict__ s_in,
             const float* __restrict__ en_w1, const float* __restrict__ en_b1,
             const float* __restrict__ en_w2, const float* __restrict__ en_b2,
             const float* __restrict__ oa_w1, const float* __restrict__ oa_b1,
             const float* __restrict__ oa_w2, const float* __restrict__ oa_b2,
             const float* __restrict__ oa_g,  const float* __restrict__ oa_bln,
             const float* __restrict__ g_w1,  const float* __restrict__ g_b1,
             const float* __restrict__ g_w2,  const float* __restrict__ g_b2,
             const float* __restrict__ g_g,   const float* __restrict__ g_bln,
             const float* __restrict__ m_w1,  const float* __restrict__ m_b1,
             const float* __restrict__ m_w2,  const float* __restrict__ m_b2,
             const float* __restrict__ m_w3,  const float* __restrict__ m_b3,
             float* __restrict__ out, int B)
{
    extern __shared__ __align__(16) float smem[];
    float* xs = smem;                              // ROWS*OBS = 6096 floats
    float* hbufA = xs + ROWS * OBS;                // ROWS*HB = 1680
    float* hbufB = hbufA + ROWS * HB;              // 1680
    SW* sw = reinterpret_cast<SW*>(hbufB + ROWS * HB);

    const int tid = threadIdx.x;

    // ---- coalesced input staging (tail zero-filled) ----
    {
        const size_t base = (size_t)blockIdx.x * ROWS * OBS;
        const size_t tot = (size_t)B * OBS;
        const float4* src4 = reinterpret_cast<const float4*>(s_in + base);
        float4* dst4 = reinterpret_cast<float4*>(xs);
        const int full4 = ROWS * OBS / 4;          // 1524
        int n4 = full4;
        if (base + (size_t)full4 * 4 > tot) n4 = (int)((tot - base) / 4);
        for (int i = tid; i < n4; i += NT) dst4[i] = src4[i];
        if (n4 < full4) {
            float4 z = make_float4(0.f, 0.f, 0.f, 0.f);
            for (int i = n4 + tid; i < full4; i += NT) dst4[i] = z;
        }
    }

    cp_smem(sw->en_w1, en_w1, 4 * 32, tid);
    cp_smem(sw->en_b1, en_b1, 32, tid);
    cp_smem(sw->en_w2, en_w2, 32 * 16, tid);
    cp_smem(sw->en_b2, en_b2, 16, tid);
    cp_smem(sw->oa_w1, oa_w1, 5 * 32, tid);
    cp_smem(sw->oa_b1, oa_b1, 32, tid);
    cp_smem(sw->oa_w2, oa_w2, 32 * 16, tid);
    cp_smem(sw->oa_b2, oa_b2, 16, tid);
    cp_smem(sw->oa_g, oa_g, 16, tid);
    cp_smem(sw->oa_bln, oa_bln, 16, tid);
    cp_smem(sw->g_w1, g_w1, 3 * 32, tid);
    cp_smem(sw->g_b1, g_b1, 32, tid);
    cp_smem(sw->g_w2, g_w2, 32 * 16, tid);
    cp_smem(sw->g_b2, g_b2, 16, tid);
    cp_smem(sw->g_g, g_g, 16, tid);
    cp_smem(sw->g_bln, g_bln, 16, tid);
    cp_smem(sw->m_w1, m_w1, 48 * 32, tid);
    cp_smem(sw->m_b1, m_b1, 32, tid);
    cp_smem(sw->m_w2, m_w2, 32 * 32, tid);
    cp_smem(sw->m_b2, m_b2, 32, tid);
    cp_smem(sw->m_w3, m_w3, 32 * 2, tid);
    if (tid < 2) sw->m_b3[tid] = m_b3[tid];
    __syncthreads();

    const int warp = tid >> 5;
    const int lane = tid & 31;
    const int g = lane >> 3;           // group 0..3 (row within warp)
    const int t = lane & 7;            // role 0..7
    const int rw = warp * 4 + g;       // CTA-local row 0..47
    const int row = blockIdx.x * ROWS + rw;

    const float* x = xs + rw * OBS;    // broadcast reads within group
    float* hA = hbufA + rw * HB;
    float* hB = hbufB + rw * HB;

    // ================= self encoder: 4 -> 32 -> 16 =================
    u64 sp;                            // my self_out pair {2t,2t+1}
    float self2[2];
    {
        u64 a0 = *reinterpret_cast<const u64*>(sw->en_b1 + 4 * t);
        u64 a1 = *reinterpret_cast<const u64*>(sw->en_b1 + 4 * t + 2);
#pragma unroll
        for (int k = 0; k < 4; k++) {
            u64 xv = f2splat(x[k]);
            const u64* wr = reinterpret_cast<const u64*>(sw->en_w1 + k * 32 + 4 * t);
            a0 = f2fma(xv, wr[0], a0);
            a1 = f2fma(xv, wr[1], a1);
        }
        float f0, f1, f2v, f3;
        f2unpack(a0, f0, f1); f2unpack(a1, f2v, f3);
        hA[4 * t + 0] = fmaxf(f0, 0.f);
        hA[4 * t + 1] = fmaxf(f1, 0.f);
        hA[4 * t + 2] = fmaxf(f2v, 0.f);
        hA[4 * t + 3] = fmaxf(f3, 0.f);
        __syncwarp();
        u64 acc = *reinterpret_cast<const u64*>(sw->en_b2 + 2 * t);
#pragma unroll
        for (int k = 0; k < 32; k++) {
            u64 xv = f2splat(hA[k]);
            acc = f2fma(xv, *reinterpret_cast<const u64*>(sw->en_w2 + k * 16 + 2 * t), acc);
        }
        float a, b; f2unpack(acc, a, b);
        self2[0] = fmaxf(a, 0.f); self2[1] = fmaxf(b, 0.f);
        sp = f2pack(self2[0], self2[1]);
    }

    float other2[2], food2[2];

    // ================= other-agent attention: 15 entities, K=5 =================
    {
        // hoist weights into registers (loop-invariant)
        u64 w1h[5][2], w2h[32];
#pragma unroll
        for (int k = 0; k < 5; k++) {
            const u64* wr = reinterpret_cast<const u64*>(sw->oa_w1 + k * 32 + 4 * t);
            w1h[k][0] = wr[0]; w1h[k][1] = wr[1];
        }
        const u64 b1a = *reinterpret_cast<const u64*>(sw->oa_b1 + 4 * t);
        const u64 b1b = *reinterpret_cast<const u64*>(sw->oa_b1 + 4 * t + 2);
#pragma unroll
        for (int k = 0; k < 32; k++)
            w2h[k] = *reinterpret_cast<const u64*>(sw->oa_w2 + k * 16 + 2 * t);
        const u64 b2h = *reinterpret_cast<const u64*>(sw->oa_b2 + 2 * t);

        float mm = -__int_as_float(0x7f800000);
        float l = 0.f;
        u64 at = 0ull;

#pragma unroll 1
        for (int i = 0; i < 15; i++) {
            float* hX = (i & 1) ? hA : hB;   // i=0 -> hB (hA busy from en phase)
            float in5[5];
            in5[0] = x[4 + 2 * i];
            in5[1] = x[5 + 2 * i];
            in5[2] = x[34 + 2 * i];
            in5[3] = x[35 + 2 * i];
            in5[4] = x[64 + i];

            u64 a0 = b1a, a1 = b1b;
#pragma unroll
            for (int k = 0; k < 5; k++) {
                u64 xv = f2splat(in5[k]);
                a0 = f2fma(xv, w1h[k][0], a0);
                a1 = f2fma(xv, w1h[k][1], a1);
            }
            float f0, f1, f2v, f3;
            f2unpack(a0, f0, f1); f2unpack(a1, f2v, f3);
            hX[4 * t + 0] = fmaxf(f0, 0.f);
            hX[4 * t + 1] = fmaxf(f1, 0.f);
            hX[4 * t + 2] = fmaxf(f2v, 0.f);
            hX[4 * t + 3] = fmaxf(f3, 0.f);
            __syncwarp();

            u64 acc = b2h;
#pragma unroll
            for (int k = 0; k < 32; k++)
                acc = f2fma(f2splat(hX[k]), w2h[k], acc);
            float a, b; f2unpack(acc, a, b);
            a = fmaxf(a, 0.f); b = fmaxf(b, 0.f);
            u64 e = f2pack(a, b);

            // score
            u64 d2 = f2mul(sp, e);
            float dl, dh; f2unpack(d2, dl, dh);
            float s = red8(dl + dh) * 0.25f;

            float nm = fmaxf(mm, s);
            float corr = __expf(mm - nm);
            float pw   = __expf(s - nm);
            mm = nm;
            l = l * corr + pw;
            at = f2fma(f2splat(corr), at, f2mul(f2splat(pw), e));
        }

        // layernorm + relu (16-dim, distributed 2 per lane)
        float inv = __fdividef(1.f, l);
        float a, b; f2unpack(at, a, b);
        a *= inv; b *= inv;
        float mu = red8(a + b) * (1.f / 16.f);
        float ca = a - mu, cb = b - mu;
        float var = red8(ca * ca + cb * cb) * (1.f / 16.f);
        float rs = rsqrtf(var + 1e-5f);
        other2[0] = fmaxf(ca * rs * sw->oa_g[2 * t]     + sw->oa_bln[2 * t],     0.f);
        other2[1] = fmaxf(cb * rs * sw->oa_g[2 * t + 1] + sw->oa_bln[2 * t + 1], 0.f);
    }

    // ================= food attention: 16 entities, K=3 =================
    {
        u64 w1h[3][2], w2h[32];
#pragma unroll
        for (int k = 0; k < 3; k++) {
            const u64* wr = reinterpret_cast<const u64*>(sw->g_w1 + k * 32 + 4 * t);
            w1h[k][0] = wr[0]; w1h[k][1] = wr[1];
        }
        const u64 b1a = *reinterpret_cast<const u64*>(sw->g_b1 + 4 * t);
        const u64 b1b = *reinterpret_cast<const u64*>(sw->g_b1 + 4 * t + 2);
#pragma unroll
        for (int k = 0; k < 32; k++)
            w2h[k] = *reinterpret_cast<const u64*>(sw->g_w2 + k * 16 + 2 * t);
        const u64 b2h = *reinterpret_cast<const u64*>(sw->g_b2 + 2 * t);

        float mm = -__int_as_float(0x7f800000);
        float l = 0.f;
        u64 at = 0ull;

#pragma unroll 1
        for (int i = 0; i < 16; i++) {
            float* hX = (i & 1) ? hB : hA;   // i=0 -> hA (last oa iter used hB)
            float in3[3];
            in3[0] = x[79 + 3 * i];
            in3[1] = x[80 + 3 * i];
            in3[2] = x[81 + 3 * i];

            u64 a0 = b1a, a1 = b1b;
#pragma unroll
            for (int k = 0; k < 3; k++) {
                u64 xv = f2splat(in3[k]);
                a0 = f2fma(xv, w1h[k][0], a0);
                a1 = f2fma(xv, w1h[k][1], a1);
            }
            float f0, f1, f2v, f3;
            f2unpack(a0, f0, f1); f2unpack(a1, f2v, f3);
            hX[4 * t + 0] = fmaxf(f0, 0.f);
            hX[4 * t + 1] = fmaxf(f1, 0.f);
            hX[4 * t + 2] = fmaxf(f2v, 0.f);
            hX[4 * t + 3] = fmaxf(f3, 0.f);
            __syncwarp();

            u64 acc = b2h;
#pragma unroll
            for (int k = 0; k < 32; k++)
                acc = f2fma(f2splat(hX[k]), w2h[k], acc);
            float a, b; f2unpack(acc, a, b);
            a = fmaxf(a, 0.f); b = fmaxf(b, 0.f);
            u64 e = f2pack(a, b);

            u64 d2 = f2mul(sp, e);
            float dl, dh; f2unpack(d2, dl, dh);
            float s = red8(dl + dh) * 0.25f;

            float nm = fmaxf(mm, s);
            float corr = __expf(mm - nm);
            float pw   = __expf(s - nm);
            mm = nm;
            l = l * corr + pw;
            at = f2fma(f2splat(corr), at, f2mul(f2splat(pw), e));
        }

        float inv = __fdividef(1.f, l);
        float a, b; f2unpack(at, a, b);
        a *= inv; b *= inv;
        float mu = red8(a + b) * (1.f / 16.f);
        float ca = a - mu, cb = b - mu;
        float var = red8(ca * ca + cb * cb) * (1.f / 16.f);
        float rs = rsqrtf(var + 1e-5f);
        food2[0] = fmaxf(ca * rs * sw->g_g[2 * t]     + sw->g_bln[2 * t],     0.f);
        food2[1] = fmaxf(cb * rs * sw->g_g[2 * t + 1] + sw->g_bln[2 * t + 1], 0.f);
    }

    // ================= merge head: 48 -> 32 -> 32 -> 2 =================
    __syncwarp();   // last g-loop reads must finish before overwriting buffers
    // merged layout: hA[0..15]=self, hA[16..31]=food, hB[0..15]=other
    hA[2 * t]      = self2[0];
    hA[2 * t + 1]  = self2[1];
    hA[16 + 2 * t] = food2[0];
    hA[16 + 2 * t + 1] = food2[1];
    hB[2 * t]      = other2[0];
    hB[2 * t + 1]  = other2[1];
    __syncwarp();

    float h1[4];
    {
        u64 a0 = *reinterpret_cast<const u64*>(sw->m_b1 + 4 * t);
        u64 a1 = *reinterpret_cast<const u64*>(sw->m_b1 + 4 * t + 2);
#pragma unroll
        for (int k = 0; k < 32; k++) {
            u64 xv = f2splat(hA[k]);
            const u64* wr = reinterpret_cast<const u64*>(sw->m_w1 + k * 32 + 4 * t);
            a0 = f2fma(xv, wr[0], a0);
            a1 = f2fma(xv, wr[1], a1);
        }
#pragma unroll
        for (int k = 0; k < 16; k++) {
            u64 xv = f2splat(hB[k]);
            const u64* wr = reinterpret_cast<const u64*>(sw->m_w1 + (32 + k) * 32 + 4 * t);
            a0 = f2fma(xv, wr[0], a0);
            a1 = f2fma(xv, wr[1], a1);
        }
        float f0, f1, f2v, f3;
        f2unpack(a0, f0, f1); f2unpack(a1, f2v, f3);
        h1[0] = fmaxf(f0, 0.01f * f0);
        h1[1] = fmaxf(f1, 0.01f * f1);
        h1[2] = fmaxf(f2v, 0.01f * f2v);
        h1[3] = fmaxf(f3, 0.01f * f3);
    }
    __syncwarp();   // all m1 reads of hA done before overwrite
    hA[4 * t + 0] = h1[0];
    hA[4 * t + 1] = h1[1];
    hA[4 * t + 2] = h1[2];
    hA[4 * t + 3] = h1[3];
    __syncwarp();

    float h2[4];
    {
        u64 a0 = *reinterpret_cast<const u64*>(sw->m_b2 + 4 * t);
        u64 a1 = *reinterpret_cast<const u64*>(sw->m_b2 + 4 * t + 2);
#pragma unroll
        for (int k = 0; k < 32; k++) {
            u64 xv = f2splat(hA[k]);
            const u64* wr = reinterpret_cast<const u64*>(sw->m_w2 + k * 32 + 4 * t);
            a0 = f2fma(xv, wr[0], a0);
            a1 = f2fma(xv, wr[1], a1);
        }
        float f0, f1, f2v, f3;
        f2unpack(a0, f0, f1); f2unpack(a1, f2v, f3);
        h2[0] = fmaxf(f0, 0.01f * f0);
        h2[1] = fmaxf(f1, 0.01f * f1);
        h2[2] = fmaxf(f2v, 0.01f * f2v);
        h2[3] = fmaxf(f3, 0.01f * f3);
    }

    // m3: 32 -> 2, k-split over my 4 h2 dims {4t..4t+3}, 8-lane reduce
    {
        u64 acc = 0ull;
#pragma unroll
        for (int j = 0; j < 4; j++) {
            const int k = 4 * t + j;
            acc = f2fma(f2splat(h2[j]),
                        *reinterpret_cast<const u64*>(sw->m_w3 + 2 * k), acc);
        }
        acc = f2add(acc, sh4(acc));
        acc = f2add(acc, sh2(acc));
        acc = f2add(acc, sh1(acc));
        if (t == 0 && row < B) {
            acc = f2add(acc, *reinterpret_cast<const u64*>(sw->m_b3));
            float a, b; f2unpack(acc, a, b);
            reinterpret_cast<float2*>(out)[row] = make_float2(tanhf(a), tanhf(b));
        }
    }
}

extern "C" void kernel_launch(void* const* d_in, const int* in_sizes, int n_in,
                              void* d_out, int out_size) {
    const float* s_in = (const float*)d_in[0];
    const int B = in_sizes[0] / OBS;
    const size_t shbytes =
        (size_t)(ROWS * OBS + 2 * ROWS * HB) * sizeof(float) + sizeof(SW);
    cudaFuncSetAttribute(actor_kernel,
                         cudaFuncAttributeMaxDynamicSharedMemorySize, (int)shbytes);
    dim3 grid((B + ROWS - 1) / ROWS), block(NT);
    actor_kernel<<<grid, block, shbytes>>>(
        s_in,
        (const float*)d_in[1],  (const float*)d_in[2],
        (const float*)d_in[3],  (const float*)d_in[4],
        (const float*)d_in[5],  (const float*)d_in[6],
        (const float*)d_in[7],  (const float*)d_in[8],
        (const float*)d_in[9],  (const float*)d_in[10],
        (const float*)d_in[11], (const float*)d_in[12],
        (const float*)d_in[13], (const float*)d_in[14],
        (const float*)d_in[15], (const float*)d_in[16],
        (const float*)d_in[17], (const float*)d_in[18],
        (const float*)d_in[19], (const float*)d_in[20],
        (const float*)d_in[21], (const float*)d_in[22],
        (float*)d_out, B);
}